// round 2
// baseline (speedup 1.0000x reference)
#include <cuda_runtime.h>
#include <math.h>

#define NN 50000
#define EE 800000
#define FI 32
#define TT 8
#define OO 32
#define CH 256   // FI*TT

// ---------------- scratch (static device globals; no allocs) ----------------
__device__ float g_deg[NN];
__device__ float g_dinv[NN];
__device__ int   g_cnt[NN];
__device__ int   g_cur[NN];
__device__ int   g_off[NN + 1];
__device__ int   g_src[EE];
__device__ float g_w[EE];
__device__ float g_xagg[(size_t)NN * CH];
__device__ float g_Mz[OO * FI];
__device__ float g_Mh[OO * FI];
__device__ float g_cbz[OO];
__device__ float g_cbh[OO];
__device__ float g_prob[TT];
__device__ int   g_is64;

// ---------------- dtype sniffer: int64 vs int32 edge_index ----------------
__global__ void __launch_bounds__(256) k_detect(const int* __restrict__ ei32) {
    __shared__ int anynz;
    if (threadIdx.x == 0) anynz = 0;
    __syncthreads();
    for (int i = threadIdx.x; i < 2048; i += blockDim.x) {
        if (ei32[2 * i + 1] != 0) anynz = 1;
    }
    __syncthreads();
    if (threadIdx.x == 0) g_is64 = anynz ? 0 : 1;
}

__device__ __forceinline__ int edge_at(const void* ei, long long idx, int is64) {
    return is64 ? (int)((const long long*)ei)[idx] : ((const int*)ei)[idx];
}

// ---------------- init: deg = 1 (self loop), cnt = cur = 0 ----------------
__global__ void __launch_bounds__(256) k_init() {
    int n = blockIdx.x * blockDim.x + threadIdx.x;
    if (n >= NN) return;
    g_deg[n] = 1.0f;
    g_cnt[n] = 0;
    g_cur[n] = 0;
}

// ---------------- degree + in-degree histogram over edges ----------------
__global__ void __launch_bounds__(256) k_deg_hist(const void* __restrict__ ei,
                                                  const float* __restrict__ ew) {
    int e = blockIdx.x * blockDim.x + threadIdx.x;
    if (e >= EE) return;
    int is64 = g_is64;
    int c = edge_at(ei, (long long)EE + e, is64);
    atomicAdd(&g_deg[c], ew[e]);
    atomicAdd(&g_cnt[c], 1);
}

// ---------------- dinv = rsqrt(deg) ----------------
__global__ void __launch_bounds__(256) k_dinv() {
    int n = blockIdx.x * blockDim.x + threadIdx.x;
    if (n >= NN) return;
    g_dinv[n] = rsqrtf(g_deg[n]);
}

// ---------------- single-block exclusive scan of cnt -> off ----------------
__global__ void __launch_bounds__(1024) k_scan() {
    __shared__ int wsum[32];
    __shared__ int carry_s;
    int t = threadIdx.x, lane = t & 31, wid = t >> 5;
    if (t == 0) carry_s = 0;
    __syncthreads();
    for (int base = 0; base < NN; base += 4096) {
        int idx = base + t * 4;
        int v0 = (idx + 0 < NN) ? g_cnt[idx + 0] : 0;
        int v1 = (idx + 1 < NN) ? g_cnt[idx + 1] : 0;
        int v2 = (idx + 2 < NN) ? g_cnt[idx + 2] : 0;
        int v3 = (idx + 3 < NN) ? g_cnt[idx + 3] : 0;
        int s0 = v0, s1 = s0 + v1, s2 = s1 + v2, s3 = s2 + v3;
        int inc = s3;
        #pragma unroll
        for (int d = 1; d < 32; d <<= 1) {
            int x = __shfl_up_sync(0xFFFFFFFFu, inc, d);
            if (lane >= d) inc += x;
        }
        if (lane == 31) wsum[wid] = inc;
        __syncthreads();
        if (wid == 0) {
            int w = wsum[lane];
            #pragma unroll
            for (int d = 1; d < 32; d <<= 1) {
                int x = __shfl_up_sync(0xFFFFFFFFu, w, d);
                if (lane >= d) w += x;
            }
            wsum[lane] = w;
        }
        __syncthreads();
        int warpoff = (wid > 0) ? wsum[wid - 1] : 0;
        int excl = carry_s + warpoff + (inc - s3);
        if (idx + 0 < NN) g_off[idx + 0] = excl;
        if (idx + 1 < NN) g_off[idx + 1] = excl + s0;
        if (idx + 2 < NN) g_off[idx + 2] = excl + s1;
        if (idx + 3 < NN) g_off[idx + 3] = excl + s2;
        __syncthreads();
        if (t == 0) carry_s += wsum[31];
        __syncthreads();
    }
    if (threadIdx.x == 0) g_off[NN] = EE;
}

// ---------------- CSR fill (by destination) with precomputed edge norm ----------------
__global__ void __launch_bounds__(256) k_fill(const void* __restrict__ ei,
                                              const float* __restrict__ ew) {
    int e = blockIdx.x * blockDim.x + threadIdx.x;
    if (e >= EE) return;
    int is64 = g_is64;
    int r = edge_at(ei, e, is64);
    int c = edge_at(ei, (long long)EE + e, is64);
    float nrm = g_dinv[r] * ew[e] * g_dinv[c];
    int p = atomicAdd(&g_cur[c], 1);
    int idx = g_off[c] + p;
    g_src[idx] = r;
    g_w[idx]   = nrm;
}

// ---------------- aggregation: Xagg = A_norm @ X   (one warp per node) ----------------
__global__ void __launch_bounds__(256) k_agg(const float* __restrict__ X) {
    int gw   = (blockIdx.x * blockDim.x + threadIdx.x) >> 5;
    int lane = threadIdx.x & 31;
    if (gw >= NN) return;
    int n = gw;
    float dv = g_dinv[n];
    float sn = dv * dv;  // self-loop norm (ew = 1)

    const float4* xn = (const float4*)(X + (size_t)n * CH);
    float4 a = xn[lane];
    float4 b = xn[lane + 32];
    float4 acc0 = make_float4(sn * a.x, sn * a.y, sn * a.z, sn * a.w);
    float4 acc1 = make_float4(sn * b.x, sn * b.y, sn * b.z, sn * b.w);

    int j = g_off[n], end = g_off[n + 1];
    for (; j < end; j++) {
        int   s = __ldg(&g_src[j]);
        float w = __ldg(&g_w[j]);
        const float4* xs = (const float4*)(X + (size_t)s * CH);
        float4 v0 = xs[lane];
        float4 v1 = xs[lane + 32];
        acc0.x = fmaf(w, v0.x, acc0.x); acc0.y = fmaf(w, v0.y, acc0.y);
        acc0.z = fmaf(w, v0.z, acc0.z); acc0.w = fmaf(w, v0.w, acc0.w);
        acc1.x = fmaf(w, v1.x, acc1.x); acc1.y = fmaf(w, v1.y, acc1.y);
        acc1.z = fmaf(w, v1.z, acc1.z); acc1.w = fmaf(w, v1.w, acc1.w);
    }
    float4* dst = (float4*)(g_xagg + (size_t)n * CH);
    dst[lane]      = acc0;
    dst[lane + 32] = acc1;
}

// ---------------- prep: Mz = Lz[:, :32] @ Wz, Mh = Lh[:, :32] @ Wh, biases, softmax ----------------
__global__ void __launch_bounds__(1024) k_prep(
        const float* __restrict__ Wz, const float* __restrict__ bz,
        const float* __restrict__ Wh, const float* __restrict__ bh,
        const float* __restrict__ Lz, const float* __restrict__ lzb,
        const float* __restrict__ Lh, const float* __restrict__ lhb,
        const float* __restrict__ attn) {
    int t = threadIdx.x;
    int o = t >> 5, f = t & 31;
    float mz = 0.f, mh = 0.f;
    #pragma unroll
    for (int k = 0; k < 32; k++) {
        mz += Lz[o * 64 + k] * Wz[k * 32 + f];
        mh += Lh[o * 64 + k] * Wh[k * 32 + f];
    }
    g_Mz[o * 32 + f] = mz;
    g_Mh[o * 32 + f] = mh;
    if (f == 0) {
        float cz = lzb[o], chh = lhb[o];
        for (int k = 0; k < 32; k++) {
            cz  += Lz[o * 64 + k] * bz[k];
            chh += Lh[o * 64 + k] * bh[k];
        }
        g_cbz[o] = cz;
        g_cbh[o] = chh;
    }
    if (t == 0) {
        float m = -1e30f;
        for (int i = 0; i < TT; i++) m = fmaxf(m, attn[i]);
        float e[TT], s = 0.f;
        for (int i = 0; i < TT; i++) { e[i] = __expf(attn[i] - m); s += e[i]; }
        float inv = 1.0f / s;
        for (int i = 0; i < TT; i++) g_prob[i] = e[i] * inv;
    }
}

// ---------------- epilogue: out[n] = sum_t p_t * (1 - sigmoid(Mz x_t)) * tanh(Mh x_t) ----------------
__global__ void __launch_bounds__(256) k_epi(float* __restrict__ out) {
    __shared__ float xs[8][CH];
    int lane = threadIdx.x & 31;
    int w    = threadIdx.x >> 5;

    float mz[FI], mh[FI];
    #pragma unroll
    for (int f = 0; f < FI; f++) {
        mz[f] = g_Mz[lane * FI + f];
        mh[f] = g_Mh[lane * FI + f];
    }
    float cbz = g_cbz[lane], cbh = g_cbh[lane];
    float pr[TT];
    #pragma unroll
    for (int t = 0; t < TT; t++) pr[t] = g_prob[t];

    int gwarp  = blockIdx.x * 8 + w;
    int nwarps = gridDim.x * 8;
    for (int n = gwarp; n < NN; n += nwarps) {
        const float4* src = (const float4*)(g_xagg + (size_t)n * CH);
        float4 a = src[lane];
        float4 b = src[lane + 32];
        __syncwarp();
        *(float4*)&xs[w][lane * 4]       = a;
        *(float4*)&xs[w][128 + lane * 4] = b;
        __syncwarp();

        float az[TT], ah[TT];
        #pragma unroll
        for (int t = 0; t < TT; t++) { az[t] = cbz; ah[t] = cbh; }

        // xs layout: index f*8 + t (matches X's [F, T] row-major inner layout)
        #pragma unroll
        for (int f = 0; f < FI; f++) {
            float4 q0 = *(const float4*)&xs[w][f * 8];
            float4 q1 = *(const float4*)&xs[w][f * 8 + 4];
            float m1 = mz[f], m2 = mh[f];
            az[0] = fmaf(m1, q0.x, az[0]); az[1] = fmaf(m1, q0.y, az[1]);
            az[2] = fmaf(m1, q0.z, az[2]); az[3] = fmaf(m1, q0.w, az[3]);
            az[4] = fmaf(m1, q1.x, az[4]); az[5] = fmaf(m1, q1.y, az[5]);
            az[6] = fmaf(m1, q1.z, az[6]); az[7] = fmaf(m1, q1.w, az[7]);
            ah[0] = fmaf(m2, q0.x, ah[0]); ah[1] = fmaf(m2, q0.y, ah[1]);
            ah[2] = fmaf(m2, q0.z, ah[2]); ah[3] = fmaf(m2, q0.w, ah[3]);
            ah[4] = fmaf(m2, q1.x, ah[4]); ah[5] = fmaf(m2, q1.y, ah[5]);
            ah[6] = fmaf(m2, q1.z, ah[6]); ah[7] = fmaf(m2, q1.w, ah[7]);
        }

        float acc = 0.f;
        #pragma unroll
        for (int t = 0; t < TT; t++) {
            float z = 1.0f / (1.0f + __expf(-az[t]));
            float h = tanhf(ah[t]);
            acc = fmaf(pr[t] * (1.0f - z), h, acc);
        }
        out[(size_t)n * OO + lane] = acc;
    }
}

// ---------------- launch ----------------
extern "C" void kernel_launch(void* const* d_in, const int* in_sizes, int n_in,
                              void* d_out, int out_size) {
    const float* X    = (const float*)d_in[0];
    const void*  EI   = d_in[1];
    const float* EW   = (const float*)d_in[2];
    const float* Wz   = (const float*)d_in[3];
    const float* bz   = (const float*)d_in[4];
    // d_in[5], d_in[6] (Wr, br): dead — R gate multiplies H == 0
    const float* Wh   = (const float*)d_in[7];
    const float* bh   = (const float*)d_in[8];
    const float* Lz   = (const float*)d_in[9];
    const float* lzb  = (const float*)d_in[10];
    // d_in[11], d_in[12] (Lr, lr_b): dead
    const float* Lh   = (const float*)d_in[13];
    const float* lhb  = (const float*)d_in[14];
    const float* attn = (const float*)d_in[15];
    float* out = (float*)d_out;

    k_detect<<<1, 256>>>((const int*)EI);
    k_init<<<(NN + 255) / 256, 256>>>();
    k_deg_hist<<<(EE + 255) / 256, 256>>>(EI, EW);
    k_dinv<<<(NN + 255) / 256, 256>>>();
    k_scan<<<1, 1024>>>();
    k_fill<<<(EE + 255) / 256, 256>>>(EI, EW);
    k_prep<<<1, 1024>>>(Wz, bz, Wh, bh, Lz, lzb, Lh, lhb, attn);
    k_agg<<<(NN * 32 + 255) / 256, 256>>>(X);
    k_epi<<<592, 256>>>(out);
}

// round 3
// speedup vs baseline: 1.4626x; 1.4626x over previous
#include <cuda_runtime.h>
#include <math.h>

#define NN 50000
#define EE 800000
#define FI 32
#define TT 8
#define OO 32
#define CH 256   // FI*TT
#define SB 49    // scan blocks: ceil(50000/1024)

// ---------------- scratch (static device globals; no allocs) ----------------
__device__ float g_deg[NN];
__device__ float g_dinv[NN];
__device__ int   g_cnt[NN];
__device__ int   g_cur[NN];
__device__ int   g_off[NN + 1];
__device__ int   g_bsum[SB];
__device__ int   g_bbase[SB];
__device__ int   g_src[EE];
__device__ float g_w[EE];
__device__ float g_MzT[FI * OO];   // transposed: [f][o]
__device__ float g_MhT[FI * OO];
__device__ float g_cbz[OO];
__device__ float g_cbh[OO];
__device__ float g_prob[TT];
__device__ int   g_is64;

// ---------------- dtype sniffer: int64 vs int32 edge_index ----------------
__global__ void __launch_bounds__(256) k_detect(const int* __restrict__ ei32) {
    __shared__ int anynz;
    if (threadIdx.x == 0) anynz = 0;
    __syncthreads();
    for (int i = threadIdx.x; i < 2048; i += blockDim.x) {
        if (ei32[2 * i + 1] != 0) anynz = 1;
    }
    __syncthreads();
    if (threadIdx.x == 0) g_is64 = anynz ? 0 : 1;
}

__device__ __forceinline__ int edge_at(const void* ei, long long idx, int is64) {
    return is64 ? (int)((const long long*)ei)[idx] : ((const int*)ei)[idx];
}

// ---------------- init: deg = 1 (self loop), cnt = 0 ----------------
__global__ void __launch_bounds__(256) k_init() {
    int n = blockIdx.x * blockDim.x + threadIdx.x;
    if (n >= NN) return;
    g_deg[n] = 1.0f;
    g_cnt[n] = 0;
}

// ---------------- degree + in-degree histogram over edges ----------------
__global__ void __launch_bounds__(256) k_deg_hist(const void* __restrict__ ei,
                                                  const float* __restrict__ ew) {
    int e = blockIdx.x * blockDim.x + threadIdx.x;
    if (e >= EE) return;
    int is64 = g_is64;
    int c = edge_at(ei, (long long)EE + e, is64);
    atomicAdd(&g_deg[c], ew[e]);
    atomicAdd(&g_cnt[c], 1);
}

// ---------------- scan stage 1: per-block count sums, fused dinv ----------------
__global__ void __launch_bounds__(1024) k_scan1() {
    __shared__ int wsum[32];
    int t = threadIdx.x, lane = t & 31, wid = t >> 5;
    int idx = blockIdx.x * 1024 + t;
    int v = 0;
    if (idx < NN) {
        v = g_cnt[idx];
        g_dinv[idx] = rsqrtf(g_deg[idx]);
    }
    int s = v;
    #pragma unroll
    for (int d = 16; d > 0; d >>= 1) s += __shfl_down_sync(0xFFFFFFFFu, s, d);
    if (lane == 0) wsum[wid] = s;
    __syncthreads();
    if (wid == 0) {
        int x = wsum[lane];
        #pragma unroll
        for (int d = 16; d > 0; d >>= 1) x += __shfl_down_sync(0xFFFFFFFFu, x, d);
        if (lane == 0) g_bsum[blockIdx.x] = x;
    }
}

// ---------------- scan stage 2: exclusive scan of SB block sums ----------------
__global__ void __launch_bounds__(32) k_scan2() {
    if (threadIdx.x == 0) {
        int acc = 0;
        for (int b = 0; b < SB; b++) {
            g_bbase[b] = acc;
            acc += g_bsum[b];
        }
    }
}

// ---------------- scan stage 3: per-node offsets; g_cur seeded = g_off ----------------
__global__ void __launch_bounds__(1024) k_scan3() {
    __shared__ int wsum[32];
    int t = threadIdx.x, lane = t & 31, wid = t >> 5;
    int idx = blockIdx.x * 1024 + t;
    int v = (idx < NN) ? g_cnt[idx] : 0;
    int inc = v;
    #pragma unroll
    for (int d = 1; d < 32; d <<= 1) {
        int x = __shfl_up_sync(0xFFFFFFFFu, inc, d);
        if (lane >= d) inc += x;
    }
    if (lane == 31) wsum[wid] = inc;
    __syncthreads();
    if (wid == 0) {
        int w = wsum[lane];
        #pragma unroll
        for (int d = 1; d < 32; d <<= 1) {
            int x = __shfl_up_sync(0xFFFFFFFFu, w, d);
            if (lane >= d) w += x;
        }
        wsum[lane] = w;
    }
    __syncthreads();
    int warpoff = (wid > 0) ? wsum[wid - 1] : 0;
    int excl = g_bbase[blockIdx.x] + warpoff + (inc - v);
    if (idx < NN) {
        g_off[idx] = excl;
        g_cur[idx] = excl;
    }
    if (idx == NN - 1) g_off[NN] = EE;
}

// ---------------- CSR fill: slot pointer = g_cur (pre-seeded to g_off) ----------------
__global__ void __launch_bounds__(256) k_fill(const void* __restrict__ ei,
                                              const float* __restrict__ ew) {
    int e = blockIdx.x * blockDim.x + threadIdx.x;
    if (e >= EE) return;
    int is64 = g_is64;
    int r = edge_at(ei, e, is64);
    int c = edge_at(ei, (long long)EE + e, is64);
    float nrm = g_dinv[r] * ew[e] * g_dinv[c];
    int idx = atomicAdd(&g_cur[c], 1);
    g_src[idx] = r;
    g_w[idx]   = nrm;
}

// ---------------- prep: MzT = (Lz[:, :32] @ Wz)^T etc., biases, softmax ----------------
__global__ void __launch_bounds__(1024) k_prep(
        const float* __restrict__ Wz, const float* __restrict__ bz,
        const float* __restrict__ Wh, const float* __restrict__ bh,
        const float* __restrict__ Lz, const float* __restrict__ lzb,
        const float* __restrict__ Lh, const float* __restrict__ lhb,
        const float* __restrict__ attn) {
    int t = threadIdx.x;
    int o = t >> 5, f = t & 31;
    float mz = 0.f, mh = 0.f;
    #pragma unroll
    for (int k = 0; k < 32; k++) {
        mz += Lz[o * 64 + k] * Wz[k * 32 + f];
        mh += Lh[o * 64 + k] * Wh[k * 32 + f];
    }
    g_MzT[f * 32 + o] = mz;   // transposed store
    g_MhT[f * 32 + o] = mh;
    if (f == 0) {
        float cz = lzb[o], chh = lhb[o];
        for (int k = 0; k < 32; k++) {
            cz  += Lz[o * 64 + k] * bz[k];
            chh += Lh[o * 64 + k] * bh[k];
        }
        g_cbz[o] = cz;
        g_cbh[o] = chh;
    }
    if (t == 0) {
        float m = -1e30f;
        for (int i = 0; i < TT; i++) m = fmaxf(m, attn[i]);
        float e[TT], s = 0.f;
        for (int i = 0; i < TT; i++) { e[i] = __expf(attn[i] - m); s += e[i]; }
        float inv = 1.0f / s;
        for (int i = 0; i < TT; i++) g_prob[i] = e[i] * inv;
    }
}

// ---------------- fused: aggregation + gated epilogue, one warp per node ----------------
// out[n,o] = sum_t p_t * (1 - sigmoid((Mz xagg_n)_{o,t})) * tanh((Mh xagg_n)_{o,t})
__global__ void __launch_bounds__(256) k_fused(const float* __restrict__ X,
                                               float* __restrict__ out) {
    __shared__ float MzT[FI * OO];
    __shared__ float MhT[FI * OO];
    __shared__ float cbz_s[OO], cbh_s[OO], pr_s[TT];
    __shared__ float xs[8][CH];

    int t = threadIdx.x;
    for (int i = t; i < FI * OO; i += 256) {
        MzT[i] = g_MzT[i];
        MhT[i] = g_MhT[i];
    }
    if (t < OO) { cbz_s[t] = g_cbz[t]; cbh_s[t] = g_cbh[t]; }
    if (t < TT) pr_s[t] = g_prob[t];
    __syncthreads();

    int w = t >> 5, lane = t & 31;
    int n = blockIdx.x * 8 + w;          // grid = 6250 blocks -> exactly 50000

    // ---- aggregation phase ----
    float dv = g_dinv[n];
    float sn = dv * dv;                  // self-loop norm (ew = 1)
    const float4* xn = (const float4*)(X + (size_t)n * CH);
    float4 a = xn[lane];
    float4 b = xn[lane + 32];
    float4 acc0 = make_float4(sn * a.x, sn * a.y, sn * a.z, sn * a.w);
    float4 acc1 = make_float4(sn * b.x, sn * b.y, sn * b.z, sn * b.w);

    int j = g_off[n], end = g_off[n + 1];
    for (; j < end; j++) {
        int   s  = __ldg(&g_src[j]);
        float wt = __ldg(&g_w[j]);
        const float4* xsrc = (const float4*)(X + (size_t)s * CH);
        float4 v0 = xsrc[lane];
        float4 v1 = xsrc[lane + 32];
        acc0.x = fmaf(wt, v0.x, acc0.x); acc0.y = fmaf(wt, v0.y, acc0.y);
        acc0.z = fmaf(wt, v0.z, acc0.z); acc0.w = fmaf(wt, v0.w, acc0.w);
        acc1.x = fmaf(wt, v1.x, acc1.x); acc1.y = fmaf(wt, v1.y, acc1.y);
        acc1.z = fmaf(wt, v1.z, acc1.z); acc1.w = fmaf(wt, v1.w, acc1.w);
    }

    // ---- stage x into shared (channel layout f*8 + t) ----
    *(float4*)&xs[w][lane * 4]       = acc0;
    *(float4*)&xs[w][128 + lane * 4] = acc1;
    __syncwarp();

    // ---- epilogue: 2x (32x32 matvec) x 8 timesteps, lane = output o ----
    float az[TT], ah[TT];
    float cbz = cbz_s[lane], cbh = cbh_s[lane];
    #pragma unroll
    for (int tt = 0; tt < TT; tt++) { az[tt] = cbz; ah[tt] = cbh; }

    #pragma unroll
    for (int f = 0; f < FI; f++) {
        float4 q0 = *(const float4*)&xs[w][f * 8];
        float4 q1 = *(const float4*)&xs[w][f * 8 + 4];
        float m1 = MzT[f * 32 + lane];
        float m2 = MhT[f * 32 + lane];
        az[0] = fmaf(m1, q0.x, az[0]); az[1] = fmaf(m1, q0.y, az[1]);
        az[2] = fmaf(m1, q0.z, az[2]); az[3] = fmaf(m1, q0.w, az[3]);
        az[4] = fmaf(m1, q1.x, az[4]); az[5] = fmaf(m1, q1.y, az[5]);
        az[6] = fmaf(m1, q1.z, az[6]); az[7] = fmaf(m1, q1.w, az[7]);
        ah[0] = fmaf(m2, q0.x, ah[0]); ah[1] = fmaf(m2, q0.y, ah[1]);
        ah[2] = fmaf(m2, q0.z, ah[2]); ah[3] = fmaf(m2, q0.w, ah[3]);
        ah[4] = fmaf(m2, q1.x, ah[4]); ah[5] = fmaf(m2, q1.y, ah[5]);
        ah[6] = fmaf(m2, q1.z, ah[6]); ah[7] = fmaf(m2, q1.w, ah[7]);
    }

    float acc = 0.f;
    #pragma unroll
    for (int tt = 0; tt < TT; tt++) {
        float z = 1.0f / (1.0f + __expf(-az[tt]));
        float h = tanhf(ah[tt]);
        acc = fmaf(pr_s[tt] * (1.0f - z), h, acc);
    }
    out[(size_t)n * OO + lane] = acc;
}

// ---------------- launch ----------------
extern "C" void kernel_launch(void* const* d_in, const int* in_sizes, int n_in,
                              void* d_out, int out_size) {
    const float* X    = (const float*)d_in[0];
    const void*  EI   = d_in[1];
    const float* EW   = (const float*)d_in[2];
    const float* Wz   = (const float*)d_in[3];
    const float* bz   = (const float*)d_in[4];
    // d_in[5], d_in[6] (Wr, br): dead — R gate multiplies H == 0
    const float* Wh   = (const float*)d_in[7];
    const float* bh   = (const float*)d_in[8];
    const float* Lz   = (const float*)d_in[9];
    const float* lzb  = (const float*)d_in[10];
    // d_in[11], d_in[12] (Lr, lr_b): dead
    const float* Lh   = (const float*)d_in[13];
    const float* lhb  = (const float*)d_in[14];
    const float* attn = (const float*)d_in[15];
    float* out = (float*)d_out;

    k_detect<<<1, 256>>>((const int*)EI);
    k_init<<<(NN + 255) / 256, 256>>>();
    k_deg_hist<<<(EE + 255) / 256, 256>>>(EI, EW);
    k_scan1<<<SB, 1024>>>();
    k_scan2<<<1, 32>>>();
    k_scan3<<<SB, 1024>>>();
    k_prep<<<1, 1024>>>(Wz, bz, Wh, bh, Lz, lzb, Lh, lhb, attn);
    k_fill<<<(EE + 255) / 256, 256>>>(EI, EW);
    k_fused<<<NN / 8, 256>>>(X, out);
}